// round 15
// baseline (speedup 1.0000x reference)
#include <cuda_runtime.h>
#include <cuda_fp16.h>
#include <cstdint>

// Problem constants
#define VOCAB 8192
#define HID   256
#define BATCH 32
#define SEQ   256
#define G3H   768   // 3*HID

// ---------------------------------------------------------------------------
// Scratch (static device globals; allocation inside kernel_launch is banned)
// ---------------------------------------------------------------------------
__device__ float  g_WT[(size_t)VOCAB * G3H];       // W_ih^T with b_ih folded: [V][768]
__device__ __half g_Y [(size_t)SEQ * BATCH * HID]; // GRU outputs, fp16, row m = t*B+b
__device__ __half g_Wd[(size_t)VOCAB * HID];       // W_dense in fp16

// ---------------------------------------------------------------------------
// PTX helpers — base-family features only (plain sm_103 target: no tcgen05).
// ---------------------------------------------------------------------------
__device__ __forceinline__ uint32_t smem_to_u32(const void* p) {
    uint32_t a;
    asm("{ .reg .u64 t; cvta.to.shared.u64 t, %1; cvt.u32.u64 %0, t; }" : "=r"(a) : "l"(p));
    return a;
}
__device__ __forceinline__ uint32_t cluster_rank() {
    uint32_t r; asm("mov.u32 %0, %%cluster_ctarank;" : "=r"(r)); return r;
}

#define CLUSTER_ARRIVE() asm volatile("barrier.cluster.arrive.aligned;" ::: "memory")
#define CLUSTER_WAIT()   asm volatile("barrier.cluster.wait.aligned;"   ::: "memory")

#define STS_CLUSTER_F32(addr, rank, val) \
    asm volatile("{\n\t.reg .b32 ra;\n\t" \
                 "mapa.shared::cluster.u32 ra, %0, %1;\n\t" \
                 "st.shared::cluster.f32 [ra], %2;\n\t}" \
                 :: "r"(addr), "r"(rank), "f"(val) : "memory")

#define FMA2(d, a, b, cc) \
    asm("fma.rn.f32x2 %0, %1, %2, %3;" : "=l"(d) : "l"(a), "l"(b), "l"(cc))

__device__ __forceinline__ unsigned long long pack_f32x2(float lo, float hi) {
    unsigned long long r;
    asm("mov.b64 %0, {%1, %2};" : "=l"(r) : "f"(lo), "f"(hi));
    return r;
}
__device__ __forceinline__ void unpack_f32x2(unsigned long long v, float& lo, float& hi) {
    asm("mov.b64 {%0, %1}, %2;" : "=f"(lo), "=f"(hi) : "l"(v));
}

// mma.sync m16n8k16 fp16 x fp16 -> fp32 (sm_80-base)
#define MMA_16816(c, a, b) \
    asm volatile("mma.sync.aligned.m16n8k16.row.col.f32.f16.f16.f32 " \
                 "{%0,%1,%2,%3}, {%4,%5,%6,%7}, {%8,%9}, {%0,%1,%2,%3};" \
                 : "+f"((c)[0]), "+f"((c)[1]), "+f"((c)[2]), "+f"((c)[3]) \
                 : "r"((a)[0]), "r"((a)[1]), "r"((a)[2]), "r"((a)[3]), \
                   "r"((b)[0]), "r"((b)[1]))

#define LDMATRIX_X4(r, addr) \
    asm volatile("ldmatrix.sync.aligned.m8n8.x4.shared.b16 {%0,%1,%2,%3}, [%4];" \
                 : "=r"((r)[0]), "=r"((r)[1]), "=r"((r)[2]), "=r"((r)[3]) \
                 : "r"(addr))

#define CP_ASYNC16(dst_u32, src_ptr) \
    asm volatile("cp.async.cg.shared.global [%0], [%1], 16;" \
                 :: "r"(dst_u32), "l"(src_ptr))
#define CP_ASYNC_COMMIT() asm volatile("cp.async.commit_group;" ::: "memory")

// ---------------------------------------------------------------------------
// Kernel 1: WT[v][j] = W_ih[j][v] + b_ih[j]   (tiled transpose, fused bias)
// ---------------------------------------------------------------------------
__global__ void transpose_wih_kernel(const float* __restrict__ W_ih,
                                     const float* __restrict__ b_ih) {
    __shared__ float tile[32][33];
    const int v0 = blockIdx.x * 32;
    const int j0 = blockIdx.y * 32;
    const int tx = threadIdx.x, ty = threadIdx.y;
    #pragma unroll
    for (int i = 0; i < 32; i += 8) {
        int j = j0 + ty + i;
        tile[ty + i][tx] = W_ih[(size_t)j * VOCAB + v0 + tx];
    }
    __syncthreads();
    #pragma unroll
    for (int i = 0; i < 32; i += 8) {
        int v = v0 + ty + i;
        int j = j0 + tx;
        g_WT[(size_t)v * G3H + j] = tile[tx][ty + i] + b_ih[j];
    }
}

// ---------------------------------------------------------------------------
// Kernel 2: W_dense fp32 -> fp16
// ---------------------------------------------------------------------------
__global__ void convert_wd_kernel(const float* __restrict__ W_dense) {
    int i = blockIdx.x * blockDim.x + threadIdx.x;
    if (i < VOCAB * HID) g_Wd[i] = __float2half(W_dense[i]);
}

// ---------------------------------------------------------------------------
// Kernel 3: GRU recurrence — FROZEN at R14 state (measured ~287us).
// 32 clusters x 4 CTAs, W_hh register-resident as f32x2, one cluster
// barrier/step, local-quarter pre-dot computed in the post-arrive shadow,
// PHYS() per-32-float padding for conflict-free LDS.128.
// ---------------------------------------------------------------------------
#define PHYS(k) ((k) + (((k) >> 5) << 2))
#define HROW 288

__global__ void __launch_bounds__(384, 1) __cluster_dims__(4, 1, 1)
gru_kernel(const int* __restrict__ X, const float* __restrict__ state,
           const float* __restrict__ W_hh, const float* __restrict__ b_hh,
           float* __restrict__ out_state) {
    __shared__ __align__(16) float hbuf[2][HROW];
    __shared__ float ghs[192];
    __shared__ int sX[SEQ];

    const int tid = threadIdx.x;
    const int c = (int)cluster_rank();
    const int b = blockIdx.x >> 2;

    const int half = tid & 1;                 // 32-float sub-run within a quarter
    const int out_local = tid >> 1;           // 0..191
    const int row = (out_local >> 6) * 256 + c * 64 + (out_local & 63);
    const int slot = c * 64 + (tid & 63);     // logical slot (tid<64 use)
    const int pslot = PHYS(slot);             // physical position in hbuf row

    // Weight slice as 64 packed f32x2, grouped by run:
    //   w2[0..15]        <- local run:  floats c*64 + half*32 + [0..32)
    //   w2[16+16t..+15]  <- remote run t: quarter q=(c+1+t)&3, q*64+half*32+[0..32)
    unsigned long long w2[64];
    {
        const float* wr = W_hh + (size_t)row * HID;
        const int kb = c * 64 + half * 32;
        #pragma unroll
        for (int i = 0; i < 8; i++) {
            float4 v = *(const float4*)(wr + kb + 4 * i);
            w2[2 * i]     = pack_f32x2(v.x, v.y);
            w2[2 * i + 1] = pack_f32x2(v.z, v.w);
        }
        #pragma unroll
        for (int t = 0; t < 3; t++) {
            const int qb = ((c + 1 + t) & 3) * 64 + half * 32;
            #pragma unroll
            for (int i = 0; i < 8; i++) {
                float4 v = *(const float4*)(wr + qb + 4 * i);
                w2[16 + 16 * t + 2 * i]     = pack_f32x2(v.x, v.y);
                w2[16 + 16 * t + 2 * i + 1] = pack_f32x2(v.z, v.w);
            }
        }
    }
    const float bhh = b_hh[row];

    if (tid < 256) hbuf[0][PHYS(tid)] = state[b * HID + tid];
    for (int i = tid; i < SEQ; i += 384) sX[i] = X[b * SEQ + i];
    __syncthreads();

    // gx prefetch for t=0
    float xr = 0.f, xz = 0.f, xn = 0.f;
    if (tid < 64) {
        const float* gxp = g_WT + (size_t)sX[0] * G3H + c * 64 + tid;
        xr = gxp[0]; xz = gxp[256]; xn = gxp[512];
    }

    // Pre-dot for t=0 over the local run (hbuf[0] local quarter is loaded)
    const int pre_off = PHYS(c * 64 + half * 32);
    unsigned long long acc0 = 0ull, acc1 = 0ull;
    {
        const ulonglong2* hl = (const ulonglong2*)(&hbuf[0][pre_off]);
        #pragma unroll
        for (int i = 0; i < 8; i++) {
            ulonglong2 hv = hl[i];
            FMA2(acc0, w2[2 * i],     hv.x, acc0);
            FMA2(acc1, w2[2 * i + 1], hv.y, acc1);
        }
    }

    CLUSTER_ARRIVE();
    const uint32_t hbuf_u32 = smem_to_u32(hbuf);

    for (int t = 0; t < SEQ; t++) {
        const int p = t & 1;
        CLUSTER_WAIT();                        // hbuf[p] remote quarters ready

        // Post-dot: 3 remote runs (acc carries the local pre-partial)
        #pragma unroll
        for (int tq = 0; tq < 3; tq++) {
            const int qb = PHYS(((c + 1 + tq) & 3) * 64 + half * 32);
            const ulonglong2* hq = (const ulonglong2*)(&hbuf[p][qb]);
            #pragma unroll
            for (int i = 0; i < 8; i++) {
                ulonglong2 hv = hq[i];
                FMA2(acc0, w2[16 + 16 * tq + 2 * i],     hv.x, acc0);
                FMA2(acc1, w2[16 + 16 * tq + 2 * i + 1], hv.y, acc1);
            }
        }
        float l0, h0, l1, h1;
        unpack_f32x2(acc0, l0, h0);
        unpack_f32x2(acc1, l1, h1);
        float acc = (l0 + h0) + (l1 + h1);
        acc += __shfl_xor_sync(0xffffffffu, acc, 1);   // combine the two sub-runs
        if (!half) ghs[out_local] = acc + bhh;
        __syncthreads();

        float hnew = 0.f;
        if (tid < 64) {
            const float hr = ghs[tid], hz = ghs[64 + tid], hn = ghs[128 + tid];
            const float r = __fdividef(1.f, 1.f + __expf(-(xr + hr)));
            const float z = __fdividef(1.f, 1.f + __expf(-(xz + hz)));
            const float y = xn + r * hn;
            const float n = 1.f - __fdividef(2.f, __expf(2.f * y) + 1.f);
            const float hp = hbuf[p][pslot];
            hnew = n + z * (hp - n);                    // (1-z)*n + z*h

            hbuf[p ^ 1][pslot] = hnew;                  // local
            const uint32_t a = hbuf_u32 + (uint32_t)((((p ^ 1) * HROW) + pslot) * 4);
            #pragma unroll
            for (int r2 = 0; r2 < 4; r2++)
                if (r2 != c) STS_CLUSTER_F32(a, r2, hnew);
        }

        CLUSTER_ARRIVE();                      // release h_new to peers
        __syncthreads();                       // gate writes visible to all threads

        // Shadow (under barrier propagation): pre-dot for t+1 on local quarter
        acc0 = 0ull; acc1 = 0ull;
        {
            const ulonglong2* hl = (const ulonglong2*)(&hbuf[p ^ 1][pre_off]);
            #pragma unroll
            for (int i = 0; i < 8; i++) {
                ulonglong2 hv = hl[i];
                FMA2(acc0, w2[2 * i],     hv.x, acc0);
                FMA2(acc1, w2[2 * i + 1], hv.y, acc1);
            }
        }
        if (tid < 64) {
            g_Y[((size_t)(t * BATCH + b)) * HID + slot] = __float2half(hnew);
            if (t == SEQ - 1) {
                out_state[b * HID + slot] = hnew;
            } else {
                const float* gxp = g_WT + (size_t)sX[t + 1] * G3H + c * 64 + tid;
                xr = gxp[0]; xz = gxp[256]; xn = gxp[512];
            }
        }
    }
    CLUSTER_WAIT();   // all peer DSMEM writes landed before any CTA exits
}

// ---------------------------------------------------------------------------
// Kernel 4: dense output GEMM via mma.sync (HMMA), fp16 in / fp32 accumulate.
// NEW: CTA tile 64(M) x 128(N), 2 warps of 64x64 (the measured-best warp
// tile), 64 threads, 4 CTAs/SM -> 16 warps/SM (was 8). Attacks the exposed
// LDSM/MMA latency (issue=14%, occ=12%) WITHOUT shrinking the warp tile
// (R10's mistake). B L2 traffic rises 256->512MB; R12 showed L2 volume was
// not binding at 58%. Same per-output K order -> bit-identical result.
// BK=32 cp.async double-buffer, fragments front-loaded, 8x8 supertile swizzle.
// ---------------------------------------------------------------------------
__global__ void __launch_bounds__(64, 4)
dense_kernel(const float* __restrict__ b_dense, float* __restrict__ out) {
    __shared__ __half sA[2][64][40];
    __shared__ __half sB[2][128][40];
    __shared__ float sbias[128];

    const int tid = threadIdx.x;
    const int wid = tid >> 5;       // 0..1
    const int lane = tid & 31;

    // 8x8 supertile swizzle over the 128(m) x 64(n) tile grid (8192 CTAs)
    const int bid = blockIdx.y * gridDim.x + blockIdx.x;
    const int st = bid >> 6;                  // 0..127
    const int within = bid & 63;
    const int n_tile = (st & 7) * 8 + (within & 7);    // 0..63
    const int m_tile = (st >> 3) * 8 + (within >> 3);  // 0..127
    const int n0 = n_tile * 128;
    const int m0 = m_tile * 64;

    const int wn = wid;             // 0..1 -> cols wn*64 (warp spans all 64 M rows)

    float c[4][8][4] = {};

    sbias[tid] = b_dense[n0 + tid];
    sbias[64 + tid] = b_dense[n0 + 64 + tid];

    // Fill one BK=32 buffer: A 64 rows x 64B (256 chunks), B 128 rows x 64B (512)
    auto fill = [&](int kb, int buf) {
        const int ko = kb * 32;
        #pragma unroll
        for (int i = 0; i < 4; i++) {
            const int chunk = i * 64 + tid;        // 0..255
            const int r = chunk >> 2;
            const int g = (chunk & 3) * 8;
            CP_ASYNC16(smem_to_u32(&sA[buf][r][g]),
                       (const void*)(g_Y + (size_t)(m0 + r) * HID + ko + g));
        }
        #pragma unroll
        for (int i = 0; i < 8; i++) {
            const int chunk = i * 64 + tid;        // 0..511
            const int r = chunk >> 2;
            const int g = (chunk & 3) * 8;
            CP_ASYNC16(smem_to_u32(&sB[buf][r][g]),
                       (const void*)(g_Wd + (size_t)(n0 + r) * HID + ko + g));
        }
        CP_ASYNC_COMMIT();
    };

    fill(0, 0);
    #pragma unroll
    for (int kb = 0; kb < 8; kb++) {
        const int buf = kb & 1;
        asm volatile("cp.async.wait_group 0;" ::: "memory");
        __syncthreads();
        if (kb < 7) fill(kb + 1, buf ^ 1);

        uint32_t a[2][4][4];
        uint32_t bfr[2][8][2];
        #pragma unroll
        for (int s = 0; s < 2; s++) {
            const int kk = s * 16;
            #pragma unroll
            for (int mt = 0; mt < 4; mt++) {
                uint32_t addr = smem_to_u32(
                    &sA[buf][mt * 16 + (lane & 15)][(lane >> 4) * 8 + kk]);
                LDMATRIX_X4(a[s][mt], addr);
            }
            #pragma unroll
            for (int nt2 = 0; nt2 < 4; nt2++) {
                uint32_t r4[4];
                uint32_t addr = smem_to_u32(
                    &sB[buf][wn * 64 + nt2 * 16 + ((lane >> 4) << 3) + (lane & 7)]
                            [((lane >> 3) & 1) * 8 + kk]);
                LDMATRIX_X4(r4, addr);
                bfr[s][2 * nt2][0] = r4[0];     bfr[s][2 * nt2][1] = r4[1];
                bfr[s][2 * nt2 + 1][0] = r4[2]; bfr[s][2 * nt2 + 1][1] = r4[3];
            }
        }
        #pragma unroll
        for (int s = 0; s < 2; s++)
            #pragma unroll
            for (int mt = 0; mt < 4; mt++)
                #pragma unroll
                for (int nt = 0; nt < 8; nt++)
                    MMA_16816(c[mt][nt], a[s][mt], bfr[s][nt]);
    }

    // Epilogue: +bias, v2 stores (fragment: row=lane/4(+8), col=(lane%4)*2)
    const int er = lane >> 2;
    const int ec = (lane & 3) * 2;
    #pragma unroll
    for (int mt = 0; mt < 4; mt++) {
        const size_t row0 = (size_t)(m0 + mt * 16 + er);
        #pragma unroll
        for (int nt = 0; nt < 8; nt++) {
            const int cl = wn * 64 + nt * 8 + ec;
            const float b0 = sbias[cl], b1 = sbias[cl + 1];
            float2 v0 = make_float2(c[mt][nt][0] + b0, c[mt][nt][1] + b1);
            float2 v1 = make_float2(c[mt][nt][2] + b0, c[mt][nt][3] + b1);
            *(float2*)&out[row0 * VOCAB + n0 + cl] = v0;
            *(float2*)&out[(row0 + 8) * VOCAB + n0 + cl] = v1;
        }
    }
}

// ---------------------------------------------------------------------------
// kernel_launch — graph-capturable, allocation-free
// Inputs: X(i32), state, W_ih, W_hh, b_ih, b_hh, W_dense, b_dense
// Output: [8192*8192 fp32 logits][32*256 fp32 final state]
// ---------------------------------------------------------------------------
extern "C" void kernel_launch(void* const* d_in, const int* in_sizes, int n_in,
                              void* d_out, int out_size) {
    const int*   X       = (const int*)  d_in[0];
    const float* state   = (const float*)d_in[1];
    const float* W_ih    = (const float*)d_in[2];
    const float* W_hh    = (const float*)d_in[3];
    const float* b_ih    = (const float*)d_in[4];
    const float* b_hh    = (const float*)d_in[5];
    const float* W_dense = (const float*)d_in[6];
    const float* b_dense = (const float*)d_in[7];
    float* out = (float*)d_out;
    float* out_state = out + (size_t)SEQ * BATCH * VOCAB;

    transpose_wih_kernel<<<dim3(VOCAB / 32, G3H / 32), dim3(32, 8)>>>(W_ih, b_ih);
    convert_wd_kernel<<<(VOCAB * HID + 1023) / 1024, 1024>>>(W_dense);
    gru_kernel<<<BATCH * 4, 384>>>(X, state, W_hh, b_hh, out_state);
    dense_kernel<<<dim3(VOCAB / 128, SEQ * BATCH / 64), 64>>>(b_dense, out);
}

// round 16
// speedup vs baseline: 1.0327x; 1.0327x over previous
#include <cuda_runtime.h>
#include <cuda_fp16.h>
#include <cstdint>

// Problem constants
#define VOCAB 8192
#define HID   256
#define BATCH 32
#define SEQ   256
#define G3H   768   // 3*HID

// ---------------------------------------------------------------------------
// Scratch (static device globals; allocation inside kernel_launch is banned)
// ---------------------------------------------------------------------------
__device__ float  g_WT[(size_t)VOCAB * G3H];       // W_ih^T with b_ih folded: [V][768]
__device__ __half g_Y [(size_t)SEQ * BATCH * HID]; // GRU outputs, fp16, row m = t*B+b
__device__ __half g_Wd[(size_t)VOCAB * HID];       // W_dense in fp16

// ---------------------------------------------------------------------------
// PTX helpers — base-family features only (plain sm_103 target: no tcgen05).
// ---------------------------------------------------------------------------
__device__ __forceinline__ uint32_t smem_to_u32(const void* p) {
    uint32_t a;
    asm("{ .reg .u64 t; cvta.to.shared.u64 t, %1; cvt.u32.u64 %0, t; }" : "=r"(a) : "l"(p));
    return a;
}
__device__ __forceinline__ uint32_t cluster_rank() {
    uint32_t r; asm("mov.u32 %0, %%cluster_ctarank;" : "=r"(r)); return r;
}

#define CLUSTER_ARRIVE() asm volatile("barrier.cluster.arrive.aligned;" ::: "memory")
#define CLUSTER_WAIT()   asm volatile("barrier.cluster.wait.aligned;"   ::: "memory")

#define STS_CLUSTER_F32(addr, rank, val) \
    asm volatile("{\n\t.reg .b32 ra;\n\t" \
                 "mapa.shared::cluster.u32 ra, %0, %1;\n\t" \
                 "st.shared::cluster.f32 [ra], %2;\n\t}" \
                 :: "r"(addr), "r"(rank), "f"(val) : "memory")

#define FMA2(d, a, b, cc) \
    asm("fma.rn.f32x2 %0, %1, %2, %3;" : "=l"(d) : "l"(a), "l"(b), "l"(cc))

__device__ __forceinline__ unsigned long long pack_f32x2(float lo, float hi) {
    unsigned long long r;
    asm("mov.b64 %0, {%1, %2};" : "=l"(r) : "f"(lo), "f"(hi));
    return r;
}
__device__ __forceinline__ void unpack_f32x2(unsigned long long v, float& lo, float& hi) {
    asm("mov.b64 {%0, %1}, %2;" : "=f"(lo), "=f"(hi) : "l"(v));
}

// mma.sync m16n8k16 fp16 x fp16 -> fp32 (sm_80-base)
#define MMA_16816(c, a, b) \
    asm volatile("mma.sync.aligned.m16n8k16.row.col.f32.f16.f16.f32 " \
                 "{%0,%1,%2,%3}, {%4,%5,%6,%7}, {%8,%9}, {%0,%1,%2,%3};" \
                 : "+f"((c)[0]), "+f"((c)[1]), "+f"((c)[2]), "+f"((c)[3]) \
                 : "r"((a)[0]), "r"((a)[1]), "r"((a)[2]), "r"((a)[3]), \
                   "r"((b)[0]), "r"((b)[1]))

#define LDMATRIX_X4(r, addr) \
    asm volatile("ldmatrix.sync.aligned.m8n8.x4.shared.b16 {%0,%1,%2,%3}, [%4];" \
                 : "=r"((r)[0]), "=r"((r)[1]), "=r"((r)[2]), "=r"((r)[3]) \
                 : "r"(addr))

#define CP_ASYNC16(dst_u32, src_ptr) \
    asm volatile("cp.async.cg.shared.global [%0], [%1], 16;" \
                 :: "r"(dst_u32), "l"(src_ptr))
#define CP_ASYNC_COMMIT() asm volatile("cp.async.commit_group;" ::: "memory")

// ---------------------------------------------------------------------------
// Kernel 1 (fused prologue):
//   blockIdx.y < 24 : WT[v][j] = W_ih[j][v] + b_ih[j] (tiled transpose+bias)
//   blockIdx.y == 24: W_dense fp32 -> fp16 (vectorized float4 -> half4)
// One launch instead of two; removes a serialization gap.
// ---------------------------------------------------------------------------
__global__ void prologue_kernel(const float* __restrict__ W_ih,
                                const float* __restrict__ b_ih,
                                const float* __restrict__ W_dense) {
    if (blockIdx.y < 24) {
        __shared__ float tile[32][33];
        const int v0 = blockIdx.x * 32;
        const int j0 = blockIdx.y * 32;
        const int tx = threadIdx.x, ty = threadIdx.y;
        #pragma unroll
        for (int i = 0; i < 32; i += 8) {
            int j = j0 + ty + i;
            tile[ty + i][tx] = W_ih[(size_t)j * VOCAB + v0 + tx];
        }
        __syncthreads();
        #pragma unroll
        for (int i = 0; i < 32; i += 8) {
            int v = v0 + ty + i;
            int j = j0 + tx;
            g_WT[(size_t)v * G3H + j] = tile[tx][ty + i] + b_ih[j];
        }
    } else {
        // 256 blocks x 256 threads cover VOCAB*HID = 2M floats: 8 float4 each
        const int tid = threadIdx.y * 32 + threadIdx.x;
        const int base4 = (blockIdx.x * 256 + tid) * 8;   // in float4 units
        #pragma unroll
        for (int i = 0; i < 8; i++) {
            const int i4 = base4 + i;                     // < 524288
            float4 v = ((const float4*)W_dense)[i4];
            __half h0 = __float2half(v.x), h1 = __float2half(v.y);
            __half h2 = __float2half(v.z), h3 = __float2half(v.w);
            ((ushort4*)g_Wd)[i4] = make_ushort4(__half_as_ushort(h0),
                                                __half_as_ushort(h1),
                                                __half_as_ushort(h2),
                                                __half_as_ushort(h3));
        }
    }
}

// ---------------------------------------------------------------------------
// Kernel 3: GRU recurrence — FROZEN at R14 state (measured ~287us).
// 32 clusters x 4 CTAs, W_hh register-resident as f32x2, one cluster
// barrier/step, local-quarter pre-dot computed in the post-arrive shadow,
// PHYS() per-32-float padding for conflict-free LDS.128.
// ---------------------------------------------------------------------------
#define PHYS(k) ((k) + (((k) >> 5) << 2))
#define HROW 288

__global__ void __launch_bounds__(384, 1) __cluster_dims__(4, 1, 1)
gru_kernel(const int* __restrict__ X, const float* __restrict__ state,
           const float* __restrict__ W_hh, const float* __restrict__ b_hh,
           float* __restrict__ out_state) {
    __shared__ __align__(16) float hbuf[2][HROW];
    __shared__ float ghs[192];
    __shared__ int sX[SEQ];

    const int tid = threadIdx.x;
    const int c = (int)cluster_rank();
    const int b = blockIdx.x >> 2;

    const int half = tid & 1;                 // 32-float sub-run within a quarter
    const int out_local = tid >> 1;           // 0..191
    const int row = (out_local >> 6) * 256 + c * 64 + (out_local & 63);
    const int slot = c * 64 + (tid & 63);     // logical slot (tid<64 use)
    const int pslot = PHYS(slot);             // physical position in hbuf row

    // Weight slice as 64 packed f32x2, grouped by run:
    //   w2[0..15]        <- local run:  floats c*64 + half*32 + [0..32)
    //   w2[16+16t..+15]  <- remote run t: quarter q=(c+1+t)&3, q*64+half*32+[0..32)
    unsigned long long w2[64];
    {
        const float* wr = W_hh + (size_t)row * HID;
        const int kb = c * 64 + half * 32;
        #pragma unroll
        for (int i = 0; i < 8; i++) {
            float4 v = *(const float4*)(wr + kb + 4 * i);
            w2[2 * i]     = pack_f32x2(v.x, v.y);
            w2[2 * i + 1] = pack_f32x2(v.z, v.w);
        }
        #pragma unroll
        for (int t = 0; t < 3; t++) {
            const int qb = ((c + 1 + t) & 3) * 64 + half * 32;
            #pragma unroll
            for (int i = 0; i < 8; i++) {
                float4 v = *(const float4*)(wr + qb + 4 * i);
                w2[16 + 16 * t + 2 * i]     = pack_f32x2(v.x, v.y);
                w2[16 + 16 * t + 2 * i + 1] = pack_f32x2(v.z, v.w);
            }
        }
    }
    const float bhh = b_hh[row];

    if (tid < 256) hbuf[0][PHYS(tid)] = state[b * HID + tid];
    for (int i = tid; i < SEQ; i += 384) sX[i] = X[b * SEQ + i];
    __syncthreads();

    // gx prefetch for t=0
    float xr = 0.f, xz = 0.f, xn = 0.f;
    if (tid < 64) {
        const float* gxp = g_WT + (size_t)sX[0] * G3H + c * 64 + tid;
        xr = gxp[0]; xz = gxp[256]; xn = gxp[512];
    }

    // Pre-dot for t=0 over the local run (hbuf[0] local quarter is loaded)
    const int pre_off = PHYS(c * 64 + half * 32);
    unsigned long long acc0 = 0ull, acc1 = 0ull;
    {
        const ulonglong2* hl = (const ulonglong2*)(&hbuf[0][pre_off]);
        #pragma unroll
        for (int i = 0; i < 8; i++) {
            ulonglong2 hv = hl[i];
            FMA2(acc0, w2[2 * i],     hv.x, acc0);
            FMA2(acc1, w2[2 * i + 1], hv.y, acc1);
        }
    }

    CLUSTER_ARRIVE();
    const uint32_t hbuf_u32 = smem_to_u32(hbuf);

    for (int t = 0; t < SEQ; t++) {
        const int p = t & 1;
        CLUSTER_WAIT();                        // hbuf[p] remote quarters ready

        // Post-dot: 3 remote runs (acc carries the local pre-partial)
        #pragma unroll
        for (int tq = 0; tq < 3; tq++) {
            const int qb = PHYS(((c + 1 + tq) & 3) * 64 + half * 32);
            const ulonglong2* hq = (const ulonglong2*)(&hbuf[p][qb]);
            #pragma unroll
            for (int i = 0; i < 8; i++) {
                ulonglong2 hv = hq[i];
                FMA2(acc0, w2[16 + 16 * tq + 2 * i],     hv.x, acc0);
                FMA2(acc1, w2[16 + 16 * tq + 2 * i + 1], hv.y, acc1);
            }
        }
        float l0, h0, l1, h1;
        unpack_f32x2(acc0, l0, h0);
        unpack_f32x2(acc1, l1, h1);
        float acc = (l0 + h0) + (l1 + h1);
        acc += __shfl_xor_sync(0xffffffffu, acc, 1);   // combine the two sub-runs
        if (!half) ghs[out_local] = acc + bhh;
        __syncthreads();

        float hnew = 0.f;
        if (tid < 64) {
            const float hr = ghs[tid], hz = ghs[64 + tid], hn = ghs[128 + tid];
            const float r = __fdividef(1.f, 1.f + __expf(-(xr + hr)));
            const float z = __fdividef(1.f, 1.f + __expf(-(xz + hz)));
            const float y = xn + r * hn;
            const float n = 1.f - __fdividef(2.f, __expf(2.f * y) + 1.f);
            const float hp = hbuf[p][pslot];
            hnew = n + z * (hp - n);                    // (1-z)*n + z*h

            hbuf[p ^ 1][pslot] = hnew;                  // local
            const uint32_t a = hbuf_u32 + (uint32_t)((((p ^ 1) * HROW) + pslot) * 4);
            #pragma unroll
            for (int r2 = 0; r2 < 4; r2++)
                if (r2 != c) STS_CLUSTER_F32(a, r2, hnew);
        }

        CLUSTER_ARRIVE();                      // release h_new to peers
        __syncthreads();                       // gate writes visible to all threads

        // Shadow (under barrier propagation): pre-dot for t+1 on local quarter
        acc0 = 0ull; acc1 = 0ull;
        {
            const ulonglong2* hl = (const ulonglong2*)(&hbuf[p ^ 1][pre_off]);
            #pragma unroll
            for (int i = 0; i < 8; i++) {
                ulonglong2 hv = hl[i];
                FMA2(acc0, w2[2 * i],     hv.x, acc0);
                FMA2(acc1, w2[2 * i + 1], hv.y, acc1);
            }
        }
        if (tid < 64) {
            g_Y[((size_t)(t * BATCH + b)) * HID + slot] = __float2half(hnew);
            if (t == SEQ - 1) {
                out_state[b * HID + slot] = hnew;
            } else {
                const float* gxp = g_WT + (size_t)sX[t + 1] * G3H + c * 64 + tid;
                xr = gxp[0]; xz = gxp[256]; xn = gxp[512];
            }
        }
    }
    CLUSTER_WAIT();   // all peer DSMEM writes landed before any CTA exits
}

// ---------------------------------------------------------------------------
// Kernel 4: dense output GEMM — R7-exact (measured 120.1-120.8us over 4 runs;
// at the legacy mma.sync HMMA roofline for 34.4GF: dense is CLOSED).
// CTA 128x128, 4 warps of 64x64, BK=32 double-buffer, fragments front-loaded,
// 8x8 supertile swizzle.
// ---------------------------------------------------------------------------
__global__ void __launch_bounds__(128, 2)
dense_kernel(const float* __restrict__ b_dense, float* __restrict__ out) {
    __shared__ __half sA[2][128][40];
    __shared__ __half sB[2][128][40];
    __shared__ float sbias[128];

    const int tid = threadIdx.x;
    const int wid = tid >> 5;
    const int lane = tid & 31;

    const int bid = blockIdx.y * gridDim.x + blockIdx.x;
    const int st = bid >> 6;
    const int within = bid & 63;
    const int n_tile = (st & 7) * 8 + (within & 7);
    const int m_tile = (st >> 3) * 8 + (within >> 3);
    const int n0 = n_tile * 128;
    const int m0 = m_tile * 128;

    const int wm = wid >> 1;
    const int wn = wid & 1;

    float c[4][8][4] = {};

    sbias[tid] = b_dense[n0 + tid];

    auto fill = [&](int kb, int buf) {
        const int ko = kb * 32;
        #pragma unroll
        for (int i = 0; i < 4; i++) {
            const int chunk = i * 128 + tid;
            const int r = chunk >> 2;
            const int g = (chunk & 3) * 8;
            CP_ASYNC16(smem_to_u32(&sA[buf][r][g]),
                       (const void*)(g_Y + (size_t)(m0 + r) * HID + ko + g));
            CP_ASYNC16(smem_to_u32(&sB[buf][r][g]),
                       (const void*)(g_Wd + (size_t)(n0 + r) * HID + ko + g));
        }
        CP_ASYNC_COMMIT();
    };

    fill(0, 0);
    #pragma unroll
    for (int kb = 0; kb < 8; kb++) {
        const int buf = kb & 1;
        asm volatile("cp.async.wait_group 0;" ::: "memory");
        __syncthreads();
        if (kb < 7) fill(kb + 1, buf ^ 1);

        uint32_t a[2][4][4];
        uint32_t bfr[2][8][2];
        #pragma unroll
        for (int s = 0; s < 2; s++) {
            const int kk = s * 16;
            #pragma unroll
            for (int mt = 0; mt < 4; mt++) {
                uint32_t addr = smem_to_u32(
                    &sA[buf][wm * 64 + mt * 16 + (lane & 15)][(lane >> 4) * 8 + kk]);
                LDMATRIX_X4(a[s][mt], addr);
            }
            #pragma unroll
            for (int nt2 = 0; nt2 < 4; nt2++) {
                uint32_t r4[4];
                uint32_t addr = smem_to_u32(
                    &sB[buf][wn * 64 + nt2 * 16 + ((lane >> 4) << 3) + (lane & 7)]
                            [((lane >> 3) & 1) * 8 + kk]);
                LDMATRIX_X4(r4, addr);
                bfr[s][2 * nt2][0] = r4[0];     bfr[s][2 * nt2][1] = r4[1];
                bfr[s][2 * nt2 + 1][0] = r4[2]; bfr[s][2 * nt2 + 1][1] = r4[3];
            }
        }
        #pragma unroll
        for (int s = 0; s < 2; s++)
            #pragma unroll
            for (int mt = 0; mt < 4; mt++)
                #pragma unroll
                for (int nt = 0; nt < 8; nt++)
                    MMA_16816(c[mt][nt], a[s][mt], bfr[s][nt]);
    }

    const int er = lane >> 2;
    const int ec = (lane & 3) * 2;
    #pragma unroll
    for (int mt = 0; mt < 4; mt++) {
        const size_t row0 = (size_t)(m0 + wm * 64 + mt * 16 + er);
        #pragma unroll
        for (int nt = 0; nt < 8; nt++) {
            const int cl = wn * 64 + nt * 8 + ec;
            const float b0 = sbias[cl], b1 = sbias[cl + 1];
            float2 v0 = make_float2(c[mt][nt][0] + b0, c[mt][nt][1] + b1);
            float2 v1 = make_float2(c[mt][nt][2] + b0, c[mt][nt][3] + b1);
            *(float2*)&out[row0 * VOCAB + n0 + cl] = v0;
            *(float2*)&out[(row0 + 8) * VOCAB + n0 + cl] = v1;
        }
    }
}

// ---------------------------------------------------------------------------
// kernel_launch — graph-capturable, allocation-free
// Inputs: X(i32), state, W_ih, W_hh, b_ih, b_hh, W_dense, b_dense
// Output: [8192*8192 fp32 logits][32*256 fp32 final state]
// ---------------------------------------------------------------------------
extern "C" void kernel_launch(void* const* d_in, const int* in_sizes, int n_in,
                              void* d_out, int out_size) {
    const int*   X       = (const int*)  d_in[0];
    const float* state   = (const float*)d_in[1];
    const float* W_ih    = (const float*)d_in[2];
    const float* W_hh    = (const float*)d_in[3];
    const float* b_ih    = (const float*)d_in[4];
    const float* b_hh    = (const float*)d_in[5];
    const float* W_dense = (const float*)d_in[6];
    const float* b_dense = (const float*)d_in[7];
    float* out = (float*)d_out;
    float* out_state = out + (size_t)SEQ * BATCH * VOCAB;

    prologue_kernel<<<dim3(VOCAB / 32, 25), dim3(32, 8)>>>(W_ih, b_ih, W_dense);
    gru_kernel<<<BATCH * 4, 384>>>(X, state, W_hh, b_hh, out_state);
    dense_kernel<<<dim3(VOCAB / 128, SEQ * BATCH / 128), 128>>>(b_dense, out);
}